// round 9
// baseline (speedup 1.0000x reference)
#include <cuda_runtime.h>

// Problem dims (fixed): B=8, N=1024, C=256, H=4, D=64
#define Bb   8
#define Nn   1024
#define Cc   256
#define Hh   4
#define Dd   64
#define HD   256               // H*D
#define ROWS (Bb * Nn)         // 8192
#define NEG_SLOPE 0.2f
#define KMAX 1040              // Nn padded to multiple of 16

// Scratch (device globals: allocation-free rule)
__device__ float g_Wx[ROWS * HD];   // 8 MB
__device__ float g_ei[ROWS * Hh];
__device__ float g_ej[ROWS * Hh];

// ---------------------------------------------------------------------------
// Kernel 1: Wx = x @ W  (8192x256 @ 256x256), 128x64 tiles, 8x4 per thread,
// DOUBLE-BUFFERED smem (1 sync per k-tile), fused e_i/e_j epilogue.
// ---------------------------------------------------------------------------
__global__ void __launch_bounds__(256) gemm_fused_k(const float* __restrict__ A,
                                                    const float* __restrict__ Bm,
                                                    const float* __restrict__ avec) {
    __shared__ float As[2][16][132];     // k-major, padded
    __shared__ float Bs[2][16][68];
    __shared__ float s_ai[64], s_aj[64];

    const int tid = threadIdx.x;
    const int tx = tid & 15;          // 0..15 -> 4 cols each
    const int ty = tid >> 4;          // 0..15 -> 8 rows each
    const int row0 = blockIdx.x * 128;
    const int col0 = blockIdx.y * 64;
    const int h = blockIdx.y;         // head index

    if (tid < 64) {
        s_ai[tid] = avec[h * 128 + tid];
        s_aj[tid] = avec[h * 128 + 64 + tid];
    }

    float acc[8][4] = {};

    const int ar = tid >> 1;
    const int ac = (tid & 1) * 8;
    const int br = tid >> 4;
    const int bc = (tid & 15) * 4;

    const float* aptr = &A[(size_t)(row0 + ar) * Cc + ac];
    const float* bptr = &Bm[(size_t)br * HD + col0 + bc];

    // load tile 0 into buffer 0
    float4 a0 = *(const float4*)(aptr);
    float4 a1 = *(const float4*)(aptr + 4);
    float4 bv = *(const float4*)(bptr);
    As[0][ac + 0][ar] = a0.x; As[0][ac + 1][ar] = a0.y;
    As[0][ac + 2][ar] = a0.z; As[0][ac + 3][ar] = a0.w;
    As[0][ac + 4][ar] = a1.x; As[0][ac + 5][ar] = a1.y;
    As[0][ac + 6][ar] = a1.z; As[0][ac + 7][ar] = a1.w;
    *(float4*)&Bs[0][br][bc] = bv;
    __syncthreads();

#pragma unroll
    for (int t = 0; t < 16; t++) {
        const int cur = t & 1;
        const int nxt = cur ^ 1;
        if (t < 15) {   // prefetch next tile (latency hidden by compute below)
            const int k0 = (t + 1) * 16;
            a0 = *(const float4*)(aptr + k0);
            a1 = *(const float4*)(aptr + k0 + 4);
            bv = *(const float4*)(bptr + (size_t)k0 * HD);
        }

#pragma unroll
        for (int kk = 0; kk < 16; kk++) {
            float4 av0 = *(float4*)&As[cur][kk][ty * 8];
            float4 av1 = *(float4*)&As[cur][kk][ty * 8 + 4];
            float4 bv4 = *(float4*)&Bs[cur][kk][tx * 4];
            float aa[8] = { av0.x, av0.y, av0.z, av0.w, av1.x, av1.y, av1.z, av1.w };
            float bb[4] = { bv4.x, bv4.y, bv4.z, bv4.w };
#pragma unroll
            for (int i = 0; i < 8; i++)
#pragma unroll
                for (int j = 0; j < 4; j++)
                    acc[i][j] = fmaf(aa[i], bb[j], acc[i][j]);
        }

        if (t < 15) {   // stage next tile into the other buffer
            As[nxt][ac + 0][ar] = a0.x; As[nxt][ac + 1][ar] = a0.y;
            As[nxt][ac + 2][ar] = a0.z; As[nxt][ac + 3][ar] = a0.w;
            As[nxt][ac + 4][ar] = a1.x; As[nxt][ac + 5][ar] = a1.y;
            As[nxt][ac + 6][ar] = a1.z; As[nxt][ac + 7][ar] = a1.w;
            *(float4*)&Bs[nxt][br][bc] = bv;
        }
        __syncthreads();
    }

    // Store Wx
#pragma unroll
    for (int i = 0; i < 8; i++) {
        float4 o = make_float4(acc[i][0], acc[i][1], acc[i][2], acc[i][3]);
        *(float4*)&g_Wx[(size_t)(row0 + ty * 8 + i) * HD + col0 + tx * 4] = o;
    }

    // Fused e_i / e_j epilogue
    float pi[8], pj[8];
#pragma unroll
    for (int i = 0; i < 8; i++) {
        float si = 0.0f, sj = 0.0f;
#pragma unroll
        for (int j = 0; j < 4; j++) {
            si = fmaf(acc[i][j], s_ai[tx * 4 + j], si);
            sj = fmaf(acc[i][j], s_aj[tx * 4 + j], sj);
        }
        pi[i] = si; pj[i] = sj;
    }
#pragma unroll
    for (int off = 8; off > 0; off >>= 1) {
#pragma unroll
        for (int i = 0; i < 8; i++) {
            pi[i] += __shfl_down_sync(0xffffffffu, pi[i], off, 16);
            pj[i] += __shfl_down_sync(0xffffffffu, pj[i], off, 16);
        }
    }
    if (tx == 0) {
#pragma unroll
        for (int i = 0; i < 8; i++) {
            int row = row0 + ty * 8 + i;
            g_ei[row * Hh + h] = pi[i];
            g_ej[row * Hh + h] = pj[i];
        }
    }
}

// ---------------------------------------------------------------------------
// Kernel 2: sparse masked softmax + float4 gather-accumulate. 1 block per (b,n)
// Planar per-head weights, K zero-padded to mult of 16, contiguous k-quarters:
// gather inner step = 1 LDS.128(idx) + 1 LDS.128(w) + 4 LDG.128 + 16 FMA.
// ---------------------------------------------------------------------------
__global__ void __launch_bounds__(256) attn_k(const float* __restrict__ adj,
                                              float* __restrict__ out) {
    __shared__ int   s_idx[KMAX];        // compacted j*64 offsets (+zero pad)
    __shared__ float s_wh[Hh][KMAX];     // per-head exp-weights (planar)
    __shared__ int   s_tot[8];
    __shared__ float s_rsum[8][4];
    __shared__ float s_acc[4][Hh * 64];  // [grp][pos*4] partial accumulators

    const int tid  = threadIdx.x;
    const int blk  = blockIdx.x;          // b*N + n
    const int b    = blk >> 10;
    const int n    = blk & 1023;
    const int warp = tid >> 5;
    const int lane = tid & 31;

    // ---- compaction: each thread owns 4 consecutive j ----
    const float4* arow4 = (const float4*)(adj + (size_t)blk * Nn);
    float4 v = arow4[tid];
    const int j0 = tid * 4;
    unsigned mk = 0;
    if (v.x != 0.0f || j0     == n) mk |= 1u;
    if (v.y != 0.0f || j0 + 1 == n) mk |= 2u;
    if (v.z != 0.0f || j0 + 2 == n) mk |= 4u;
    if (v.w != 0.0f || j0 + 3 == n) mk |= 8u;
    int cnt = __popc(mk);
    int scan = cnt;
#pragma unroll
    for (int off = 1; off < 32; off <<= 1) {
        int t = __shfl_up_sync(0xffffffffu, scan, off);
        if (lane >= off) scan += t;
    }
    if (lane == 31) s_tot[warp] = scan;
    __syncthreads();
    int base = 0, K = 0;
#pragma unroll
    for (int w = 0; w < 8; w++) {
        int t = s_tot[w];
        if (w < warp) base += t;
        K += t;
    }
    int pos0 = base + (scan - cnt);
    if (mk & 1u) s_idx[pos0++] = (j0    ) * 64;
    if (mk & 2u) s_idx[pos0++] = (j0 + 1) * 64;
    if (mk & 4u) s_idx[pos0++] = (j0 + 2) * 64;
    if (mk & 8u) s_idx[pos0++] = (j0 + 3) * 64;
    __syncthreads();

    const int Kpad = (K + 15) & ~15;

    // ---- zero-pad tail entries (idx->row0, weight 0 => no contribution) ----
    for (int k = K + tid; k < Kpad; k += 256) {
        s_idx[k] = 0;
        s_wh[0][k] = 0.0f; s_wh[1][k] = 0.0f;
        s_wh[2][k] = 0.0f; s_wh[3][k] = 0.0f;
    }

    // ---- fused score + exp + sum (no max-subtract: scores bounded, fp32-safe) ----
    float4 eiv = *(const float4*)&g_ei[blk * Hh];
    const float4* ej4 = (const float4*)g_ej;
    float lsum[4] = {};
    for (int k = tid; k < K; k += 256) {
        int j = s_idx[k] >> 6;
        float4 ejv = __ldg(&ej4[(b << 10) + j]);
        float s0 = eiv.x + ejv.x, s1 = eiv.y + ejv.y;
        float s2 = eiv.z + ejv.z, s3 = eiv.w + ejv.w;
        s0 = s0 > 0.0f ? s0 : NEG_SLOPE * s0;
        s1 = s1 > 0.0f ? s1 : NEG_SLOPE * s1;
        s2 = s2 > 0.0f ? s2 : NEG_SLOPE * s2;
        s3 = s3 > 0.0f ? s3 : NEG_SLOPE * s3;
        float w0 = __expf(s0), w1 = __expf(s1);
        float w2 = __expf(s2), w3 = __expf(s3);
        s_wh[0][k] = w0; s_wh[1][k] = w1;
        s_wh[2][k] = w2; s_wh[3][k] = w3;
        lsum[0] += w0; lsum[1] += w1; lsum[2] += w2; lsum[3] += w3;
    }
#pragma unroll
    for (int off = 16; off > 0; off >>= 1)
#pragma unroll
        for (int h = 0; h < 4; h++)
            lsum[h] += __shfl_xor_sync(0xffffffffu, lsum[h], off);
    if (lane == 0)
#pragma unroll
        for (int h = 0; h < 4; h++) s_rsum[warp][h] = lsum[h];
    __syncthreads();   // orders s_idx / s_wh writes before gather reads

    // ---- gather: pos owns out floats [4pos,4pos+4); grp takes a contiguous
    //      quarter of [0,Kpad) (multiple of 4) ----
    const int pos = tid & 63;
    const int grp = tid >> 6;
    const int hh  = pos >> 4;            // head of this float4
    const float* wrow = s_wh[hh];
    const int Q  = Kpad >> 2;            // multiple of 4
    const int lo = grp * Q, hi = lo + Q;
    const float4* wx4 = (const float4*)(g_Wx + (size_t)b * (Nn * HD));
    float4 acc = make_float4(0.f, 0.f, 0.f, 0.f);
    for (int k = lo; k < hi; k += 4) {
        int4   i4 = *(const int4*)&s_idx[k];
        float4 w4 = *(const float4*)&wrow[k];
        float4 v0 = __ldg(&wx4[i4.x + pos]);
        float4 v1 = __ldg(&wx4[i4.y + pos]);
        float4 v2 = __ldg(&wx4[i4.z + pos]);
        float4 v3 = __ldg(&wx4[i4.w + pos]);
        acc.x = fmaf(w4.x, v0.x, acc.x); acc.y = fmaf(w4.x, v0.y, acc.y);
        acc.z = fmaf(w4.x, v0.z, acc.z); acc.w = fmaf(w4.x, v0.w, acc.w);
        acc.x = fmaf(w4.y, v1.x, acc.x); acc.y = fmaf(w4.y, v1.y, acc.y);
        acc.z = fmaf(w4.y, v1.z, acc.z); acc.w = fmaf(w4.y, v1.w, acc.w);
        acc.x = fmaf(w4.z, v2.x, acc.x); acc.y = fmaf(w4.z, v2.y, acc.y);
        acc.z = fmaf(w4.z, v2.z, acc.z); acc.w = fmaf(w4.z, v2.w, acc.w);
        acc.x = fmaf(w4.w, v3.x, acc.x); acc.y = fmaf(w4.w, v3.y, acc.y);
        acc.z = fmaf(w4.w, v3.z, acc.z); acc.w = fmaf(w4.w, v3.w, acc.w);
    }
    *(float4*)&s_acc[grp][pos * 4] = acc;
    __syncthreads();

    // ---- cross-group reduce + normalize + store ----
    if (tid < 64) {
        const int h = tid >> 4;
        float4 r = *(float4*)&s_acc[0][tid * 4];
#pragma unroll
        for (int g = 1; g < 4; g++) {
            float4 t = *(float4*)&s_acc[g][tid * 4];
            r.x += t.x; r.y += t.y; r.z += t.z; r.w += t.w;
        }
        float tot = 0.0f;
#pragma unroll
        for (int w = 0; w < 8; w++) tot += s_rsum[w][h];
        float inv = 1.0f / tot;
        r.x *= inv; r.y *= inv; r.z *= inv; r.w *= inv;
        *(float4*)&out[(size_t)blk * HD + tid * 4] = r;
    }
}

// ---------------------------------------------------------------------------
extern "C" void kernel_launch(void* const* d_in, const int* in_sizes, int n_in,
                              void* d_out, int out_size) {
    const float *x = nullptr, *adj = nullptr, *W = nullptr, *a = nullptr;
    for (int i = 0; i < n_in; i++) {
        switch (in_sizes[i]) {
            case Bb * Nn * Cc:  x   = (const float*)d_in[i]; break;  // 2097152
            case Bb * Nn * Nn:  adj = (const float*)d_in[i]; break;  // 8388608
            case Cc * HD:       W   = (const float*)d_in[i]; break;  // 65536
            case Hh * 2 * Dd:   a   = (const float*)d_in[i]; break;  // 512
        }
    }
    float* out = (float*)d_out;

    dim3 ggrid(ROWS / 128, HD / 64);    // 64 x 4 = 256 blocks
    gemm_fused_k<<<ggrid, 256>>>(x, W, a);
    attn_k<<<ROWS, 256>>>(adj, out);
}

// round 10
// speedup vs baseline: 1.1139x; 1.1139x over previous
#include <cuda_runtime.h>
#include <cuda_fp16.h>

// Problem dims (fixed): B=8, N=1024, C=256, H=4, D=64
#define Bb   8
#define Nn   1024
#define Cc   256
#define Hh   4
#define Dd   64
#define HD   256               // H*D
#define ROWS (Bb * Nn)         // 8192
#define NEG_SLOPE 0.2f

// Scratch (device globals: allocation-free rule)
__device__ __half g_Wxh[ROWS * HD]; // 4 MB  (fp16 Wx — the only Wx consumer is the gather)
__device__ float  g_ei[ROWS * Hh];
__device__ float  g_ej[ROWS * Hh];

// ---------------------------------------------------------------------------
// Kernel 1: Wx = x @ W  (8192x256 @ 256x256), 128x64 tiles, 8x4 per thread,
// double-buffered smem (1 sync per k-tile), fp16 Wx store,
// fused e_i/e_j epilogue (1 head per col-tile).
// ---------------------------------------------------------------------------
__global__ void __launch_bounds__(256) gemm_fused_k(const float* __restrict__ A,
                                                    const float* __restrict__ Bm,
                                                    const float* __restrict__ avec) {
    __shared__ float As[2][16][132];     // k-major, padded
    __shared__ float Bs[2][16][68];
    __shared__ float s_ai[64], s_aj[64];

    const int tid = threadIdx.x;
    const int tx = tid & 15;          // 0..15 -> 4 cols each
    const int ty = tid >> 4;          // 0..15 -> 8 rows each
    const int row0 = blockIdx.x * 128;
    const int col0 = blockIdx.y * 64;
    const int h = blockIdx.y;         // head index

    if (tid < 64) {
        s_ai[tid] = avec[h * 128 + tid];
        s_aj[tid] = avec[h * 128 + 64 + tid];
    }

    float acc[8][4] = {};

    const int ar = tid >> 1;
    const int ac = (tid & 1) * 8;
    const int br = tid >> 4;
    const int bc = (tid & 15) * 4;

    const float* aptr = &A[(size_t)(row0 + ar) * Cc + ac];
    const float* bptr = &Bm[(size_t)br * HD + col0 + bc];

    // load tile 0 into buffer 0
    float4 a0 = *(const float4*)(aptr);
    float4 a1 = *(const float4*)(aptr + 4);
    float4 bv = *(const float4*)(bptr);
    As[0][ac + 0][ar] = a0.x; As[0][ac + 1][ar] = a0.y;
    As[0][ac + 2][ar] = a0.z; As[0][ac + 3][ar] = a0.w;
    As[0][ac + 4][ar] = a1.x; As[0][ac + 5][ar] = a1.y;
    As[0][ac + 6][ar] = a1.z; As[0][ac + 7][ar] = a1.w;
    *(float4*)&Bs[0][br][bc] = bv;
    __syncthreads();

#pragma unroll
    for (int t = 0; t < 16; t++) {
        const int cur = t & 1;
        const int nxt = cur ^ 1;
        if (t < 15) {   // prefetch next tile
            const int k0 = (t + 1) * 16;
            a0 = *(const float4*)(aptr + k0);
            a1 = *(const float4*)(aptr + k0 + 4);
            bv = *(const float4*)(bptr + (size_t)k0 * HD);
        }

#pragma unroll
        for (int kk = 0; kk < 16; kk++) {
            float4 av0 = *(float4*)&As[cur][kk][ty * 8];
            float4 av1 = *(float4*)&As[cur][kk][ty * 8 + 4];
            float4 bv4 = *(float4*)&Bs[cur][kk][tx * 4];
            float aa[8] = { av0.x, av0.y, av0.z, av0.w, av1.x, av1.y, av1.z, av1.w };
            float bb[4] = { bv4.x, bv4.y, bv4.z, bv4.w };
#pragma unroll
            for (int i = 0; i < 8; i++)
#pragma unroll
                for (int j = 0; j < 4; j++)
                    acc[i][j] = fmaf(aa[i], bb[j], acc[i][j]);
        }

        if (t < 15) {
            As[nxt][ac + 0][ar] = a0.x; As[nxt][ac + 1][ar] = a0.y;
            As[nxt][ac + 2][ar] = a0.z; As[nxt][ac + 3][ar] = a0.w;
            As[nxt][ac + 4][ar] = a1.x; As[nxt][ac + 5][ar] = a1.y;
            As[nxt][ac + 6][ar] = a1.z; As[nxt][ac + 7][ar] = a1.w;
            *(float4*)&Bs[nxt][br][bc] = bv;
        }
        __syncthreads();
    }

    // Store Wx as fp16 (8B STG per row-chunk)
#pragma unroll
    for (int i = 0; i < 8; i++) {
        __half2 h01 = __floats2half2_rn(acc[i][0], acc[i][1]);
        __half2 h23 = __floats2half2_rn(acc[i][2], acc[i][3]);
        uint2 u;
        u.x = *(unsigned int*)&h01;
        u.y = *(unsigned int*)&h23;
        *(uint2*)&g_Wxh[(size_t)(row0 + ty * 8 + i) * HD + col0 + tx * 4] = u;
    }

    // Fused e_i / e_j epilogue (fp32 accumulators)
    float pi[8], pj[8];
#pragma unroll
    for (int i = 0; i < 8; i++) {
        float si = 0.0f, sj = 0.0f;
#pragma unroll
        for (int j = 0; j < 4; j++) {
            si = fmaf(acc[i][j], s_ai[tx * 4 + j], si);
            sj = fmaf(acc[i][j], s_aj[tx * 4 + j], sj);
        }
        pi[i] = si; pj[i] = sj;
    }
#pragma unroll
    for (int off = 8; off > 0; off >>= 1) {
#pragma unroll
        for (int i = 0; i < 8; i++) {
            pi[i] += __shfl_down_sync(0xffffffffu, pi[i], off, 16);
            pj[i] += __shfl_down_sync(0xffffffffu, pj[i], off, 16);
        }
    }
    if (tx == 0) {
#pragma unroll
        for (int i = 0; i < 8; i++) {
            int row = row0 + ty * 8 + i;
            g_ei[row * Hh + h] = pi[i];
            g_ej[row * Hh + h] = pj[i];
        }
    }
}

// ---------------------------------------------------------------------------
// Kernel 2: sparse masked softmax + fp16 gather-accumulate. 1 block per (b,n)
// Round-7 structure (25KB smem, 32 regs, occ ~90%); gather loads are LDG.64
// of 4 halves (half the bytes of the fp32 version).
// ---------------------------------------------------------------------------
__global__ void __launch_bounds__(256) attn_k(const float* __restrict__ adj,
                                              float* __restrict__ out) {
    __shared__ int   s_idx[Nn];          // compacted j*64 offsets (ordered)
    __shared__ float s_w[Nn * Hh];       // [k][h] exp-weights (float4 per k)
    __shared__ int   s_tot[8];
    __shared__ float s_rsum[8][4];
    __shared__ float s_acc[4][Hh * 64];  // [grp][pos*4] partial accumulators

    const int tid  = threadIdx.x;
    const int blk  = blockIdx.x;          // b*N + n
    const int b    = blk >> 10;
    const int n    = blk & 1023;
    const int warp = tid >> 5;
    const int lane = tid & 31;

    // ---- compaction: each thread owns 4 consecutive j ----
    const float4* arow4 = (const float4*)(adj + (size_t)blk * Nn);
    float4 v = arow4[tid];
    const int j0 = tid * 4;
    unsigned mk = 0;
    if (v.x != 0.0f || j0     == n) mk |= 1u;
    if (v.y != 0.0f || j0 + 1 == n) mk |= 2u;
    if (v.z != 0.0f || j0 + 2 == n) mk |= 4u;
    if (v.w != 0.0f || j0 + 3 == n) mk |= 8u;
    int cnt = __popc(mk);
    int scan = cnt;
#pragma unroll
    for (int off = 1; off < 32; off <<= 1) {
        int t = __shfl_up_sync(0xffffffffu, scan, off);
        if (lane >= off) scan += t;
    }
    if (lane == 31) s_tot[warp] = scan;
    __syncthreads();
    int base = 0, K = 0;
#pragma unroll
    for (int w = 0; w < 8; w++) {
        int t = s_tot[w];
        if (w < warp) base += t;
        K += t;
    }
    int pos0 = base + (scan - cnt);
    if (mk & 1u) s_idx[pos0++] = (j0    ) * 64;
    if (mk & 2u) s_idx[pos0++] = (j0 + 1) * 64;
    if (mk & 4u) s_idx[pos0++] = (j0 + 2) * 64;
    if (mk & 8u) s_idx[pos0++] = (j0 + 3) * 64;
    __syncthreads();

    // ---- fused score + exp + sum (no max-subtract: scores bounded, fp32-safe) ----
    float4 eiv = *(const float4*)&g_ei[blk * Hh];
    const float4* ej4 = (const float4*)g_ej;
    float lsum[4] = {};
    for (int k = tid; k < K; k += 256) {
        int j = s_idx[k] >> 6;
        float4 ejv = __ldg(&ej4[(b << 10) + j]);
        float s0 = eiv.x + ejv.x, s1 = eiv.y + ejv.y;
        float s2 = eiv.z + ejv.z, s3 = eiv.w + ejv.w;
        s0 = s0 > 0.0f ? s0 : NEG_SLOPE * s0;
        s1 = s1 > 0.0f ? s1 : NEG_SLOPE * s1;
        s2 = s2 > 0.0f ? s2 : NEG_SLOPE * s2;
        s3 = s3 > 0.0f ? s3 : NEG_SLOPE * s3;
        float w0 = __expf(s0), w1 = __expf(s1);
        float w2 = __expf(s2), w3 = __expf(s3);
        *(float4*)&s_w[k * Hh] = make_float4(w0, w1, w2, w3);
        lsum[0] += w0; lsum[1] += w1; lsum[2] += w2; lsum[3] += w3;
    }
#pragma unroll
    for (int off = 16; off > 0; off >>= 1)
#pragma unroll
        for (int h = 0; h < 4; h++)
            lsum[h] += __shfl_xor_sync(0xffffffffu, lsum[h], off);
    if (lane == 0)
#pragma unroll
        for (int h = 0; h < 4; h++) s_rsum[warp][h] = lsum[h];
    __syncthreads();   // orders s_w / s_idx writes before gather reads

    // ---- fp16 gather: pos owns out floats [4pos,4pos+4), grp splits k ----
    const int pos = tid & 63;
    const int grp = tid >> 6;
    const int hh  = pos >> 4;            // head of this float4
    const uint2* hw = (const uint2*)(g_Wxh + (size_t)b * (Nn * HD));
    float4 acc = make_float4(0.f, 0.f, 0.f, 0.f);
    int k = grp;
    for (; k + 12 < K; k += 16) {
        int oa = s_idx[k] + pos,     ob = s_idx[k + 4]  + pos;
        int oc = s_idx[k + 8] + pos, od = s_idx[k + 12] + pos;
        float wa = s_w[(k     ) * Hh + hh], wb = s_w[(k +  4) * Hh + hh];
        float wc = s_w[(k +  8) * Hh + hh], wd = s_w[(k + 12) * Hh + hh];
        uint2 ua = __ldg(&hw[oa]);
        uint2 ub = __ldg(&hw[ob]);
        uint2 uc = __ldg(&hw[oc]);
        uint2 ud = __ldg(&hw[od]);
        float2 a0 = __half22float2(*(__half2*)&ua.x);
        float2 a1 = __half22float2(*(__half2*)&ua.y);
        float2 b0 = __half22float2(*(__half2*)&ub.x);
        float2 b1 = __half22float2(*(__half2*)&ub.y);
        float2 c0 = __half22float2(*(__half2*)&uc.x);
        float2 c1 = __half22float2(*(__half2*)&uc.y);
        float2 d0 = __half22float2(*(__half2*)&ud.x);
        float2 d1 = __half22float2(*(__half2*)&ud.y);
        acc.x = fmaf(wa, a0.x, acc.x); acc.y = fmaf(wa, a0.y, acc.y);
        acc.z = fmaf(wa, a1.x, acc.z); acc.w = fmaf(wa, a1.y, acc.w);
        acc.x = fmaf(wb, b0.x, acc.x); acc.y = fmaf(wb, b0.y, acc.y);
        acc.z = fmaf(wb, b1.x, acc.z); acc.w = fmaf(wb, b1.y, acc.w);
        acc.x = fmaf(wc, c0.x, acc.x); acc.y = fmaf(wc, c0.y, acc.y);
        acc.z = fmaf(wc, c1.x, acc.z); acc.w = fmaf(wc, c1.y, acc.w);
        acc.x = fmaf(wd, d0.x, acc.x); acc.y = fmaf(wd, d0.y, acc.y);
        acc.z = fmaf(wd, d1.x, acc.z); acc.w = fmaf(wd, d1.y, acc.w);
    }
    for (; k < K; k += 4) {
        int o = s_idx[k] + pos;
        float w = s_w[k * Hh + hh];
        uint2 uu = __ldg(&hw[o]);
        float2 l0 = __half22float2(*(__half2*)&uu.x);
        float2 l1 = __half22float2(*(__half2*)&uu.y);
        acc.x = fmaf(w, l0.x, acc.x); acc.y = fmaf(w, l0.y, acc.y);
        acc.z = fmaf(w, l1.x, acc.z); acc.w = fmaf(w, l1.y, acc.w);
    }
    *(float4*)&s_acc[grp][pos * 4] = acc;
    __syncthreads();

    // ---- cross-group reduce + normalize + store ----
    if (tid < 64) {
        const int h = tid >> 4;
        float4 r = *(float4*)&s_acc[0][tid * 4];
#pragma unroll
        for (int g = 1; g < 4; g++) {
            float4 t = *(float4*)&s_acc[g][tid * 4];
            r.x += t.x; r.y += t.y; r.z += t.z; r.w += t.w;
        }
        float tot = 0.0f;
#pragma unroll
        for (int w = 0; w < 8; w++) tot += s_rsum[w][h];
        float inv = 1.0f / tot;
        r.x *= inv; r.y *= inv; r.z *= inv; r.w *= inv;
        *(float4*)&out[(size_t)blk * HD + tid * 4] = r;
    }
}

// ---------------------------------------------------------------------------
extern "C" void kernel_launch(void* const* d_in, const int* in_sizes, int n_in,
                              void* d_out, int out_size) {
    const float *x = nullptr, *adj = nullptr, *W = nullptr, *a = nullptr;
    for (int i = 0; i < n_in; i++) {
        switch (in_sizes[i]) {
            case Bb * Nn * Cc:  x   = (const float*)d_in[i]; break;  // 2097152
            case Bb * Nn * Nn:  adj = (const float*)d_in[i]; break;  // 8388608
            case Cc * HD:       W   = (const float*)d_in[i]; break;  // 65536
            case Hh * 2 * Dd:   a   = (const float*)d_in[i]; break;  // 512
        }
    }
    float* out = (float*)d_out;

    dim3 ggrid(ROWS / 128, HD / 64);    // 64 x 4 = 256 blocks
    gemm_fused_k<<<ggrid, 256>>>(x, W, a);
    attn_k<<<ROWS, 256>>>(adj, out);
}